// round 10
// baseline (speedup 1.0000x reference)
#include <cuda_runtime.h>
#include <math.h>

// B=4, M=256, T=64; fc1: 512->512, fc_out: 1024->768
#define DOUT 768
#define NBT  256   // B*T

typedef unsigned long long u64;

__device__ __forceinline__ u64 fma2(u64 a, u64 b, u64 c) {
    u64 d; asm("fma.rn.f32x2 %0, %1, %2, %3;" : "=l"(d) : "l"(a), "l"(b), "l"(c)); return d;
}
__device__ __forceinline__ u64 add2(u64 a, u64 b) {
    u64 d; asm("add.rn.f32x2 %0, %1, %2;" : "=l"(d) : "l"(a), "l"(b)); return d;
}
__device__ __forceinline__ float2 upk(u64 a) {
    float2 f; asm("mov.b64 {%0, %1}, %2;" : "=f"(f.x), "=f"(f.y) : "l"(a)); return f;
}

__device__ float g_U2[512 * DOUT];    // interleaved: [(j*DOUT+o)*2+d] = U[2j+d, o]
__device__ float g_base[256 * DOUT];  // pos_embed @ W2[512:]
__device__ float g_C[DOUT];           // b1 @ W2[:512] + b2
__device__ float g_P0[NBT * DOUT];
__device__ float g_P1[NBT * DOUT];
__device__ float g_Q [NBT * DOUT];

// ---------------- fused GEMM, f32x2 pairs-on-n ----------------
// grid (12, 13), block 256:
//   y in [0,8):  U rows (64/block) = W1 @ W2[:512] -> g_U2 (interleaved)
//   y in [8,12): base rows (64/block) = pos_embed @ W2[512:]
//   y == 12:     C = b1 @ W2[:512] + b2
__global__ void __launch_bounds__(256) k_gemm(
        const float* __restrict__ W1, const float* __restrict__ pe,
        const float* __restrict__ W2,
        const float* __restrict__ b1, const float* __restrict__ b2) {
    const int col0 = blockIdx.x * 64;
    const int tid = threadIdx.x;

    if (blockIdx.y == 12) {
        __shared__ float red[4][64];
        const int col = tid & 63;
        const int sub = tid >> 6;          // 0..3, 128 n each
        float acc = 0.f;
        const int n0 = sub * 128;
#pragma unroll 4
        for (int i = 0; i < 128; ++i)
            acc = fmaf(b1[n0 + i], W2[(n0 + i) * DOUT + col0 + col], acc);
        red[sub][col] = acc;
        __syncthreads();
        if (sub == 0)
            g_C[col0 + col] = red[0][col] + red[1][col] + red[2][col] + red[3][col] + b2[col0 + col];
        return;
    }

    __shared__ float2 As2[16][68];   // duplicated (a,a); row stride 544B (16B-aligned)
    __shared__ float  Bs [16][68];   // scalar B; row stride 272B (16B-aligned)

    const int row0 = blockIdx.y * 64;
    const bool isU = (row0 < 512);
    const float* A = isU ? (W1 + row0 * 512) : (pe + (row0 - 512) * 512);
    const int koff = isU ? 0 : 512;

    const int tm = (tid >> 4) * 4;      // 0..60 (m)
    const int tn = (tid & 15) * 4;      // 0..60 (n)

    const int ar = tid >> 2;            // 0..63 A row within tile
    const int ac = (tid & 3) * 4;       // 0,4,8,12 k-offset
    const int bk = tid >> 6;            // 0..3
    const int bj = tid & 63;            // 0..63

    u64 acc2[4][2];
#pragma unroll
    for (int i = 0; i < 4; ++i) { acc2[i][0] = 0ull; acc2[i][1] = 0ull; }

    // register prefetch of first tiles
    float4 a4 = *(const float4*)(A + ar * 512 + ac);
    float  b4[4];
#pragma unroll
    for (int r = 0; r < 4; ++r)
        b4[r] = W2[(koff + bk + r * 4) * DOUT + col0 + bj];

    for (int k0 = 0; k0 < 512; k0 += 16) {
        As2[ac + 0][ar] = make_float2(a4.x, a4.x);
        As2[ac + 1][ar] = make_float2(a4.y, a4.y);
        As2[ac + 2][ar] = make_float2(a4.z, a4.z);
        As2[ac + 3][ar] = make_float2(a4.w, a4.w);
#pragma unroll
        for (int r = 0; r < 4; ++r)
            Bs[bk + r * 4][bj] = b4[r];
        __syncthreads();

        if (k0 + 16 < 512) {
            a4 = *(const float4*)(A + ar * 512 + k0 + 16 + ac);
#pragma unroll
            for (int r = 0; r < 4; ++r)
                b4[r] = W2[(koff + k0 + 16 + bk + r * 4) * DOUT + col0 + bj];
        }

#pragma unroll
        for (int k = 0; k < 16; ++k) {
            ulonglong2 aP0 = *(const ulonglong2*)(&As2[k][tm]);      // (a0,a0),(a1,a1)
            ulonglong2 aP1 = *(const ulonglong2*)(&As2[k][tm + 2]);  // (a2,a2),(a3,a3)
            ulonglong2 bP  = *(const ulonglong2*)(&Bs[k][tn]);       // (b0,b1),(b2,b3)
            acc2[0][0] = fma2(aP0.x, bP.x, acc2[0][0]);
            acc2[0][1] = fma2(aP0.x, bP.y, acc2[0][1]);
            acc2[1][0] = fma2(aP0.y, bP.x, acc2[1][0]);
            acc2[1][1] = fma2(aP0.y, bP.y, acc2[1][1]);
            acc2[2][0] = fma2(aP1.x, bP.x, acc2[2][0]);
            acc2[2][1] = fma2(aP1.x, bP.y, acc2[2][1]);
            acc2[3][0] = fma2(aP1.y, bP.x, acc2[3][0]);
            acc2[3][1] = fma2(aP1.y, bP.y, acc2[3][1]);
        }
        __syncthreads();
    }

    if (isU) {
#pragma unroll
        for (int i = 0; i < 4; ++i) {
            int gr = row0 + tm + i;
            int j = gr >> 1, d = gr & 1;
#pragma unroll
            for (int c = 0; c < 2; ++c) {
                float2 f = upk(acc2[i][c]);
                g_U2[(j * DOUT + col0 + tn + 2 * c)     * 2 + d] = f.x;
                g_U2[(j * DOUT + col0 + tn + 2 * c + 1) * 2 + d] = f.y;
            }
        }
    } else {
#pragma unroll
        for (int i = 0; i < 4; ++i)
            *(ulonglong2*)(g_base + (row0 - 512 + tm + i) * DOUT + col0 + tn) =
                make_ulonglong2(acc2[i][0], acc2[i][1]);
    }
}

// ---------------- P0/P1/Q per (b,t), f32x2 ----------------
#define PG 4
__global__ void __launch_bounds__(256) k_P(const float* __restrict__ coords,
                                           const float* __restrict__ vis) {
    __shared__ float2 sv2[PG][256];   // (v, v)
    __shared__ float2 sxy[PG][256];   // (v*x, v*y)
    const int grp = blockIdx.x;   // 64 groups of PG bt
    const int ot  = blockIdx.y;   // 3 o-tiles of 256
    const int tid = threadIdx.x;
    const int o = ot * 256 + tid;

    for (int e = tid; e < PG * 256; e += 256) {
        int g = e >> 8, j = e & 255;
        int bt = grp * PG + g;
        int b = bt >> 6, t = bt & 63;
        int ci = ((b * 256 + j) * 64 + t) * 2;
        float x = coords[ci], y = coords[ci + 1];
        float v = vis[(b * 256 + j) * 64 + t];
        if (isnan(x)) { v = 0.f; x = 0.f; }
        if (isnan(y)) y = 0.f;
        sv2[g][j] = make_float2(v, v);
        sxy[g][j] = make_float2(v * x, v * y);
    }
    __syncthreads();

    u64 p01[PG], q2[PG];
#pragma unroll
    for (int g = 0; g < PG; ++g) { p01[g] = 0ull; q2[g] = 0ull; }

#pragma unroll 4
    for (int j = 0; j < 256; ++j) {
        u64 u = *(const u64*)(g_U2 + (j * DOUT + o) * 2);   // (u0, u1)
#pragma unroll
        for (int g = 0; g < PG; ++g) {
            u64 v2 = *(const u64*)(&sv2[g][j]);
            u64 xy = *(const u64*)(&sxy[g][j]);
            p01[g] = fma2(v2, u, p01[g]);   // (p0 += v*u0, p1 += v*u1)
            q2[g]  = fma2(xy, u, q2[g]);    // (qx += vx*u0, qy += vy*u1)
        }
    }
#pragma unroll
    for (int g = 0; g < PG; ++g) {
        int bt = grp * PG + g;
        float2 p = upk(p01[g]);
        float2 q = upk(q2[g]);
        g_P0[bt * DOUT + o] = p.x;
        g_P1[bt * DOUT + o] = p.y;
        g_Q [bt * DOUT + o] = q.x + q.y;
    }
}

// ---------------- out[bt,m,o] = vis_m*(cx_m*P0 + cy_m*P1 - Q) + base[m,o] + C[o] ----------------
__global__ void __launch_bounds__(256) k_out(const float* __restrict__ coords,
                                             const float* __restrict__ vis,
                                             float* __restrict__ out) {
    __shared__ float2 ss0[8][16];   // (v*x, v*x)
    __shared__ float2 ss1[8][16];   // (v*y, v*y)
    __shared__ float2 ss2[8][16];   // (-v, -v)
    const int mg0 = blockIdx.x * 16;  // 16 m-groups
    const int ot  = blockIdx.y;       // 3 o-tiles (256 each)
    const int btc = blockIdx.z * 8;   // 32 bt-chunks of 8
    const int tid = threadIdx.x;

    if (tid < 128) {
        int btl = tid >> 4, ml = tid & 15;
        int bt = btc + btl;
        int b = bt >> 6, t = bt & 63;
        int m = mg0 + ml;
        int ci = ((b * 256 + m) * 64 + t) * 2;
        float x = coords[ci], y = coords[ci + 1];
        float v = vis[(b * 256 + m) * 64 + t];
        if (isnan(x)) { v = 0.f; x = 0.f; }
        if (isnan(y)) y = 0.f;
        ss0[btl][ml] = make_float2(v * x, v * x);
        ss1[btl][ml] = make_float2(v * y, v * y);
        ss2[btl][ml] = make_float2(-v, -v);
    }
    __syncthreads();

    const int oq  = tid & 63;
    const int mg  = tid >> 6;        // 0..3
    const int o   = ot * 256 + oq * 4;
    const int ml0 = mg * 4;

    ulonglong2 cc = *(const ulonglong2*)(g_C + o);
    u64 baseC[4][2];
#pragma unroll
    for (int r = 0; r < 4; ++r) {
        ulonglong2 bv = *(const ulonglong2*)(g_base + (mg0 + ml0 + r) * DOUT + o);
        baseC[r][0] = add2(bv.x, cc.x);
        baseC[r][1] = add2(bv.y, cc.y);
    }

#pragma unroll
    for (int btl = 0; btl < 8; ++btl) {
        int bt = btc + btl;
        ulonglong2 p0 = *(const ulonglong2*)(g_P0 + bt * DOUT + o);
        ulonglong2 p1 = *(const ulonglong2*)(g_P1 + bt * DOUT + o);
        ulonglong2 qv = *(const ulonglong2*)(g_Q  + bt * DOUT + o);
#pragma unroll
        for (int r = 0; r < 4; ++r) {
            u64 a2 = *(const u64*)(&ss0[btl][ml0 + r]);
            u64 b2 = *(const u64*)(&ss1[btl][ml0 + r]);
            u64 c2 = *(const u64*)(&ss2[btl][ml0 + r]);
            u64 o0 = fma2(a2, p0.x, fma2(b2, p1.x, fma2(c2, qv.x, baseC[r][0])));
            u64 o1 = fma2(a2, p0.y, fma2(b2, p1.y, fma2(c2, qv.y, baseC[r][1])));
            float* dst = out + ((bt * 256 + mg0 + ml0 + r) * DOUT) + o;
            asm volatile("st.global.cs.v2.u64 [%0], {%1, %2};"
                         :: "l"(dst), "l"(o0), "l"(o1) : "memory");
        }
    }
}

extern "C" void kernel_launch(void* const* d_in, const int* in_sizes, int n_in,
                              void* d_out, int out_size) {
    const float* coords = (const float*)d_in[0];  // (4,256,64,2)
    const float* vis    = (const float*)d_in[1];  // (4,256,64)
    const float* pe     = (const float*)d_in[2];  // (256,512)
    const float* W1     = (const float*)d_in[3];  // (512,512)
    const float* b1     = (const float*)d_in[4];  // (512,)
    const float* W2     = (const float*)d_in[5];  // (1024,768)
    const float* b2     = (const float*)d_in[6];  // (768,)
    float* out = (float*)d_out;                   // (4,64,256,768)

    k_gemm<<<dim3(12, 13), 256>>>(W1, pe, W2, b1, b2);
    k_P   <<<dim3(64, 3),  256>>>(coords, vis);
    k_out <<<dim3(16, 3, 32), 256>>>(coords, vis, out);
}

// round 12
// speedup vs baseline: 1.5698x; 1.5698x over previous
#include <cuda_runtime.h>
#include <math.h>

// B=4, M=256, T=64; fc1: 512->512, fc_out: 1024->768
#define DOUT 768
#define NBT  256   // B*T

typedef unsigned long long u64;

__device__ __forceinline__ u64 fma2(u64 a, u64 b, u64 c) {
    u64 d; asm("fma.rn.f32x2 %0, %1, %2, %3;" : "=l"(d) : "l"(a), "l"(b), "l"(c)); return d;
}
__device__ __forceinline__ u64 add2(u64 a, u64 b) {
    u64 d; asm("add.rn.f32x2 %0, %1, %2;" : "=l"(d) : "l"(a), "l"(b)); return d;
}
__device__ __forceinline__ float2 upk(u64 a) {
    float2 f; asm("mov.b64 {%0, %1}, %2;" : "=f"(f.x), "=f"(f.y) : "l"(a)); return f;
}

__device__ float g_U2[512 * DOUT];    // interleaved: [(j*DOUT+o)*2+d] = U[2j+d, o]
__device__ float g_base[256 * DOUT];  // pos_embed @ W2[512:]
__device__ float g_C[DOUT];           // b1 @ W2[:512] + b2
__device__ float g_P0[NBT * DOUT];
__device__ float g_P1[NBT * DOUT];
__device__ float g_Q [NBT * DOUT];
// split-K partials
__device__ float g_pU[2][512 * DOUT];
__device__ float g_pB[2][256 * DOUT];

// ---------------- fused GEMM, scalar FFMA, split-K over blockIdx.z ----------------
// grid (12, 13, 2), block 256:
//   y in [0,8):  U rows (64/block), K-half z -> g_pU[z] (interleaved layout)
//   y in [8,12): base rows (64/block), K-half z -> g_pB[z]
//   y == 12, z==0: C = b1 @ W2[:512] + b2 ; z==1: nothing
__global__ void __launch_bounds__(256) k_gemm(
        const float* __restrict__ W1, const float* __restrict__ pe,
        const float* __restrict__ W2,
        const float* __restrict__ b1, const float* __restrict__ b2) {
    const int col0 = blockIdx.x * 64;
    const int kz   = blockIdx.z;           // K half: 0 or 1
    const int tid  = threadIdx.x;

    if (blockIdx.y == 12) {
        if (kz == 1) return;
        __shared__ float red[4][64];
        const int col = tid & 63;
        const int sub = tid >> 6;          // 0..3, 128 n each
        float acc = 0.f;
        const int n0 = sub * 128;
#pragma unroll 4
        for (int i = 0; i < 128; ++i)
            acc = fmaf(b1[n0 + i], W2[(n0 + i) * DOUT + col0 + col], acc);
        red[sub][col] = acc;
        __syncthreads();
        if (sub == 0)
            g_C[col0 + col] = red[0][col] + red[1][col] + red[2][col] + red[3][col] + b2[col0 + col];
        return;
    }

    __shared__ float As[16][68];   // transposed A tile: As[k][m], padded
    __shared__ float Bs[16][64];   // Bs[k][n]
    const int row0 = blockIdx.y * 64;
    const bool isU = (row0 < 512);
    const float* A = (isU ? (W1 + row0 * 512) : (pe + (row0 - 512) * 512)) + kz * 256;
    const int koff = (isU ? 0 : 512) + kz * 256;

    const int tm = (tid >> 4) * 4;     // 0..60 (m within tile)
    const int tn = (tid & 15) * 4;     // 0..60 (n within tile)

    const int ar = tid >> 2;           // 0..63 A row
    const int ac = (tid & 3) * 4;      // 0,4,8,12 A k-offset
    const int bk = tid >> 6;           // 0..3
    const int bj = tid & 63;           // 0..63

    float acc[4][4];
#pragma unroll
    for (int i = 0; i < 4; ++i)
#pragma unroll
        for (int j = 0; j < 4; ++j) acc[i][j] = 0.f;

    // prefetch first tiles into registers
    float4 a4 = *(const float4*)(A + ar * 512 + ac);
    float  b4[4];
#pragma unroll
    for (int r = 0; r < 4; ++r)
        b4[r] = W2[(koff + bk + r * 4) * DOUT + col0 + bj];

    for (int k0 = 0; k0 < 256; k0 += 16) {
        As[ac + 0][ar] = a4.x;
        As[ac + 1][ar] = a4.y;
        As[ac + 2][ar] = a4.z;
        As[ac + 3][ar] = a4.w;
#pragma unroll
        for (int r = 0; r < 4; ++r)
            Bs[bk + r * 4][bj] = b4[r];
        __syncthreads();

        if (k0 + 16 < 256) {
            a4 = *(const float4*)(A + ar * 512 + k0 + 16 + ac);
#pragma unroll
            for (int r = 0; r < 4; ++r)
                b4[r] = W2[(koff + k0 + 16 + bk + r * 4) * DOUT + col0 + bj];
        }

#pragma unroll
        for (int k = 0; k < 16; ++k) {
            float4 av = *(const float4*)(&As[k][tm]);
            float4 bv = *(const float4*)(&Bs[k][tn]);
            acc[0][0] = fmaf(av.x, bv.x, acc[0][0]); acc[0][1] = fmaf(av.x, bv.y, acc[0][1]);
            acc[0][2] = fmaf(av.x, bv.z, acc[0][2]); acc[0][3] = fmaf(av.x, bv.w, acc[0][3]);
            acc[1][0] = fmaf(av.y, bv.x, acc[1][0]); acc[1][1] = fmaf(av.y, bv.y, acc[1][1]);
            acc[1][2] = fmaf(av.y, bv.z, acc[1][2]); acc[1][3] = fmaf(av.y, bv.w, acc[1][3]);
            acc[2][0] = fmaf(av.z, bv.x, acc[2][0]); acc[2][1] = fmaf(av.z, bv.y, acc[2][1]);
            acc[2][2] = fmaf(av.z, bv.z, acc[2][2]); acc[2][3] = fmaf(av.z, bv.w, acc[2][3]);
            acc[3][0] = fmaf(av.w, bv.x, acc[3][0]); acc[3][1] = fmaf(av.w, bv.y, acc[3][1]);
            acc[3][2] = fmaf(av.w, bv.z, acc[3][2]); acc[3][3] = fmaf(av.w, bv.w, acc[3][3]);
        }
        __syncthreads();
    }

    if (isU) {
        float* dst = g_pU[kz];
#pragma unroll
        for (int i = 0; i < 4; ++i) {
            int gr = row0 + tm + i;
            int j = gr >> 1, d = gr & 1;
#pragma unroll
            for (int c = 0; c < 4; ++c)
                dst[(j * DOUT + col0 + tn + c) * 2 + d] = acc[i][c];
        }
    } else {
        float* dst = g_pB[kz];
#pragma unroll
        for (int i = 0; i < 4; ++i) {
            float4 v = make_float4(acc[i][0], acc[i][1], acc[i][2], acc[i][3]);
            *(float4*)(dst + (row0 - 512 + tm + i) * DOUT + col0 + tn) = v;
        }
    }
}

// ---------------- reduce split-K partials ----------------
// 98304 float4 for U2, 49152 float4 for base; grid 576 x 256
__global__ void __launch_bounds__(256) k_red() {
    const int i = blockIdx.x * 256 + threadIdx.x;   // float4 index
    if (i < 98304) {
        float4 a = ((const float4*)g_pU[0])[i];
        float4 b = ((const float4*)g_pU[1])[i];
        ((float4*)g_U2)[i] = make_float4(a.x + b.x, a.y + b.y, a.z + b.z, a.w + b.w);
    } else {
        int j = i - 98304;
        float4 a = ((const float4*)g_pB[0])[j];
        float4 b = ((const float4*)g_pB[1])[j];
        ((float4*)g_base)[j] = make_float4(a.x + b.x, a.y + b.y, a.z + b.z, a.w + b.w);
    }
}

// ---------------- P0/P1/Q per (b,t), f32x2 ----------------
#define PG 4
__global__ void __launch_bounds__(256) k_P(const float* __restrict__ coords,
                                           const float* __restrict__ vis) {
    __shared__ float2 sv2[PG][256];   // (v, v)
    __shared__ float2 sxy[PG][256];   // (v*x, v*y)
    const int grp = blockIdx.x;   // 64 groups of PG bt
    const int ot  = blockIdx.y;   // 3 o-tiles of 256
    const int tid = threadIdx.x;
    const int o = ot * 256 + tid;

    for (int e = tid; e < PG * 256; e += 256) {
        int g = e >> 8, j = e & 255;
        int bt = grp * PG + g;
        int b = bt >> 6, t = bt & 63;
        int ci = ((b * 256 + j) * 64 + t) * 2;
        float x = coords[ci], y = coords[ci + 1];
        float v = vis[(b * 256 + j) * 64 + t];
        if (isnan(x)) { v = 0.f; x = 0.f; }
        if (isnan(y)) y = 0.f;
        sv2[g][j] = make_float2(v, v);
        sxy[g][j] = make_float2(v * x, v * y);
    }
    __syncthreads();

    u64 p01[PG], q2[PG];
#pragma unroll
    for (int g = 0; g < PG; ++g) { p01[g] = 0ull; q2[g] = 0ull; }

#pragma unroll 4
    for (int j = 0; j < 256; ++j) {
        u64 u = *(const u64*)(g_U2 + (j * DOUT + o) * 2);   // (u0, u1)
#pragma unroll
        for (int g = 0; g < PG; ++g) {
            u64 v2 = *(const u64*)(&sv2[g][j]);
            u64 xy = *(const u64*)(&sxy[g][j]);
            p01[g] = fma2(v2, u, p01[g]);   // (p0 += v*u0, p1 += v*u1)
            q2[g]  = fma2(xy, u, q2[g]);    // (qx += vx*u0, qy += vy*u1)
        }
    }
#pragma unroll
    for (int g = 0; g < PG; ++g) {
        int bt = grp * PG + g;
        float2 p = upk(p01[g]);
        float2 q = upk(q2[g]);
        g_P0[bt * DOUT + o] = p.x;
        g_P1[bt * DOUT + o] = p.y;
        g_Q [bt * DOUT + o] = q.x + q.y;
    }
}

// ---------------- out[bt,m,o] = vis_m*(cx_m*P0 + cy_m*P1 - Q) + base[m,o] + C[o] ----------------
__global__ void __launch_bounds__(256) k_out(const float* __restrict__ coords,
                                             const float* __restrict__ vis,
                                             float* __restrict__ out) {
    __shared__ float2 ss0[8][16];   // (v*x, v*x)
    __shared__ float2 ss1[8][16];   // (v*y, v*y)
    __shared__ float2 ss2[8][16];   // (-v, -v)
    const int mg0 = blockIdx.x * 16;  // 16 m-groups
    const int ot  = blockIdx.y;       // 3 o-tiles (256 each)
    const int btc = blockIdx.z * 8;   // 32 bt-chunks of 8
    const int tid = threadIdx.x;

    if (tid < 128) {
        int btl = tid >> 4, ml = tid & 15;
        int bt = btc + btl;
        int b = bt >> 6, t = bt & 63;
        int m = mg0 + ml;
        int ci = ((b * 256 + m) * 64 + t) * 2;
        float x = coords[ci], y = coords[ci + 1];
        float v = vis[(b * 256 + m) * 64 + t];
        if (isnan(x)) { v = 0.f; x = 0.f; }
        if (isnan(y)) y = 0.f;
        ss0[btl][ml] = make_float2(v * x, v * x);
        ss1[btl][ml] = make_float2(v * y, v * y);
        ss2[btl][ml] = make_float2(-v, -v);
    }
    __syncthreads();

    const int oq  = tid & 63;
    const int mg  = tid >> 6;        // 0..3
    const int o   = ot * 256 + oq * 4;
    const int ml0 = mg * 4;

    ulonglong2 cc = *(const ulonglong2*)(g_C + o);
    u64 baseC[4][2];
#pragma unroll
    for (int r = 0; r < 4; ++r) {
        ulonglong2 bv = *(const ulonglong2*)(g_base + (mg0 + ml0 + r) * DOUT + o);
        baseC[r][0] = add2(bv.x, cc.x);
        baseC[r][1] = add2(bv.y, cc.y);
    }

#pragma unroll
    for (int btl = 0; btl < 8; ++btl) {
        int bt = btc + btl;
        ulonglong2 p0 = *(const ulonglong2*)(g_P0 + bt * DOUT + o);
        ulonglong2 p1 = *(const ulonglong2*)(g_P1 + bt * DOUT + o);
        ulonglong2 qv = *(const ulonglong2*)(g_Q  + bt * DOUT + o);
#pragma unroll
        for (int r = 0; r < 4; ++r) {
            u64 a2 = *(const u64*)(&ss0[btl][ml0 + r]);
            u64 b2 = *(const u64*)(&ss1[btl][ml0 + r]);
            u64 c2 = *(const u64*)(&ss2[btl][ml0 + r]);
            u64 o0 = fma2(a2, p0.x, fma2(b2, p1.x, fma2(c2, qv.x, baseC[r][0])));
            u64 o1 = fma2(a2, p0.y, fma2(b2, p1.y, fma2(c2, qv.y, baseC[r][1])));
            float* dst = out + ((bt * 256 + mg0 + ml0 + r) * DOUT) + o;
            asm volatile("st.global.cs.v2.u64 [%0], {%1, %2};"
                         :: "l"(dst), "l"(o0), "l"(o1) : "memory");
        }
    }
}

extern "C" void kernel_launch(void* const* d_in, const int* in_sizes, int n_in,
                              void* d_out, int out_size) {
    const float* coords = (const float*)d_in[0];  // (4,256,64,2)
    const float* vis    = (const float*)d_in[1];  // (4,256,64)
    const float* pe     = (const float*)d_in[2];  // (256,512)
    const float* W1     = (const float*)d_in[3];  // (512,512)
    const float* b1     = (const float*)d_in[4];  // (512,)
    const float* W2     = (const float*)d_in[5];  // (1024,768)
    const float* b2     = (const float*)d_in[6];  // (768,)
    float* out = (float*)d_out;                   // (4,64,256,768)

    k_gemm<<<dim3(12, 13, 2), 256>>>(W1, pe, W2, b1, b2);
    k_red <<<576, 256>>>();
    k_P   <<<dim3(64, 3),  256>>>(coords, vis);
    k_out <<<dim3(16, 3, 32), 256>>>(coords, vis, out);
}

// round 14
// speedup vs baseline: 1.6112x; 1.0264x over previous
#include <cuda_runtime.h>
#include <math.h>

// B=4, M=256, T=64; fc1: 512->512, fc_out: 1024->768
#define DOUT 768
#define NBT  256   // B*T

typedef unsigned long long u64;

__device__ __forceinline__ u64 fma2(u64 a, u64 b, u64 c) {
    u64 d; asm("fma.rn.f32x2 %0, %1, %2, %3;" : "=l"(d) : "l"(a), "l"(b), "l"(c)); return d;
}
__device__ __forceinline__ u64 add2(u64 a, u64 b) {
    u64 d; asm("add.rn.f32x2 %0, %1, %2;" : "=l"(d) : "l"(a), "l"(b)); return d;
}
__device__ __forceinline__ float2 upk(u64 a) {
    float2 f; asm("mov.b64 {%0, %1}, %2;" : "=f"(f.x), "=f"(f.y) : "l"(a)); return f;
}

__device__ float g_U2[512 * DOUT];    // interleaved: [(j*DOUT+o)*2+d] = U[2j+d, o]
__device__ float g_base[256 * DOUT];  // pos_embed @ W2[512:]
__device__ float g_C[DOUT];           // b1 @ W2[:512] + b2
__device__ float g_P0[NBT * DOUT];
__device__ float g_P1[NBT * DOUT];
__device__ float g_Q [NBT * DOUT];
// split-K partials
__device__ float g_pU[2][512 * DOUT];
__device__ float g_pB[2][256 * DOUT];

// ---------------- fused GEMM, scalar FFMA, split-K over blockIdx.z ----------------
// grid (12, 13, 2), block 256:
//   y in [0,8):  U rows (64/block), K-half z -> g_pU[z] (interleaved layout)
//   y in [8,12): base rows (64/block), K-half z -> g_pB[z]
//   y == 12, z==0: C = b1 @ W2[:512] + b2 ; z==1: nothing
__global__ void __launch_bounds__(256) k_gemm(
        const float* __restrict__ W1, const float* __restrict__ pe,
        const float* __restrict__ W2,
        const float* __restrict__ b1, const float* __restrict__ b2) {
    const int col0 = blockIdx.x * 64;
    const int kz   = blockIdx.z;           // K half: 0 or 1
    const int tid  = threadIdx.x;

    if (blockIdx.y == 12) {
        if (kz == 1) return;
        __shared__ float red[4][64];
        const int col = tid & 63;
        const int sub = tid >> 6;          // 0..3, 128 n each
        float acc = 0.f;
        const int n0 = sub * 128;
#pragma unroll 4
        for (int i = 0; i < 128; ++i)
            acc = fmaf(b1[n0 + i], W2[(n0 + i) * DOUT + col0 + col], acc);
        red[sub][col] = acc;
        __syncthreads();
        if (sub == 0)
            g_C[col0 + col] = red[0][col] + red[1][col] + red[2][col] + red[3][col] + b2[col0 + col];
        return;
    }

    __shared__ float As[16][68];   // transposed A tile: As[k][m], padded
    __shared__ float Bs[16][64];   // Bs[k][n]
    const int row0 = blockIdx.y * 64;
    const bool isU = (row0 < 512);
    const float* A = (isU ? (W1 + row0 * 512) : (pe + (row0 - 512) * 512)) + kz * 256;
    const int koff = (isU ? 0 : 512) + kz * 256;

    const int tm = (tid >> 4) * 4;     // 0..60 (m within tile)
    const int tn = (tid & 15) * 4;     // 0..60 (n within tile)

    const int ar = tid >> 2;           // 0..63 A row
    const int ac = (tid & 3) * 4;      // 0,4,8,12 A k-offset
    const int bk = tid >> 6;           // 0..3
    const int bj = tid & 63;           // 0..63

    float acc[4][4];
#pragma unroll
    for (int i = 0; i < 4; ++i)
#pragma unroll
        for (int j = 0; j < 4; ++j) acc[i][j] = 0.f;

    // prefetch first tiles into registers
    float4 a4 = *(const float4*)(A + ar * 512 + ac);
    float  b4[4];
#pragma unroll
    for (int r = 0; r < 4; ++r)
        b4[r] = W2[(koff + bk + r * 4) * DOUT + col0 + bj];

    for (int k0 = 0; k0 < 256; k0 += 16) {
        As[ac + 0][ar] = a4.x;
        As[ac + 1][ar] = a4.y;
        As[ac + 2][ar] = a4.z;
        As[ac + 3][ar] = a4.w;
#pragma unroll
        for (int r = 0; r < 4; ++r)
            Bs[bk + r * 4][bj] = b4[r];
        __syncthreads();

        if (k0 + 16 < 256) {
            a4 = *(const float4*)(A + ar * 512 + k0 + 16 + ac);
#pragma unroll
            for (int r = 0; r < 4; ++r)
                b4[r] = W2[(koff + k0 + 16 + bk + r * 4) * DOUT + col0 + bj];
        }

#pragma unroll
        for (int k = 0; k < 16; ++k) {
            float4 av = *(const float4*)(&As[k][tm]);
            float4 bv = *(const float4*)(&Bs[k][tn]);
            acc[0][0] = fmaf(av.x, bv.x, acc[0][0]); acc[0][1] = fmaf(av.x, bv.y, acc[0][1]);
            acc[0][2] = fmaf(av.x, bv.z, acc[0][2]); acc[0][3] = fmaf(av.x, bv.w, acc[0][3]);
            acc[1][0] = fmaf(av.y, bv.x, acc[1][0]); acc[1][1] = fmaf(av.y, bv.y, acc[1][1]);
            acc[1][2] = fmaf(av.y, bv.z, acc[1][2]); acc[1][3] = fmaf(av.y, bv.w, acc[1][3]);
            acc[2][0] = fmaf(av.z, bv.x, acc[2][0]); acc[2][1] = fmaf(av.z, bv.y, acc[2][1]);
            acc[2][2] = fmaf(av.z, bv.z, acc[2][2]); acc[2][3] = fmaf(av.z, bv.w, acc[2][3]);
            acc[3][0] = fmaf(av.w, bv.x, acc[3][0]); acc[3][1] = fmaf(av.w, bv.y, acc[3][1]);
            acc[3][2] = fmaf(av.w, bv.z, acc[3][2]); acc[3][3] = fmaf(av.w, bv.w, acc[3][3]);
        }
        __syncthreads();
    }

    if (isU) {
        float* dst = g_pU[kz];
#pragma unroll
        for (int i = 0; i < 4; ++i) {
            int gr = row0 + tm + i;
            int j = gr >> 1, d = gr & 1;
#pragma unroll
            for (int c = 0; c < 4; ++c)
                dst[(j * DOUT + col0 + tn + c) * 2 + d] = acc[i][c];
        }
    } else {
        float* dst = g_pB[kz];
#pragma unroll
        for (int i = 0; i < 4; ++i) {
            float4 v = make_float4(acc[i][0], acc[i][1], acc[i][2], acc[i][3]);
            *(float4*)(dst + (row0 - 512 + tm + i) * DOUT + col0 + tn) = v;
        }
    }
}

// ---------------- reduce split-K partials ----------------
// 98304 float4 for U2, 49152 float4 for base; grid 576 x 256
__global__ void __launch_bounds__(256) k_red() {
    const int i = blockIdx.x * 256 + threadIdx.x;   // float4 index
    if (i < 98304) {
        float4 a = ((const float4*)g_pU[0])[i];
        float4 b = ((const float4*)g_pU[1])[i];
        ((float4*)g_U2)[i] = make_float4(a.x + b.x, a.y + b.y, a.z + b.z, a.w + b.w);
    } else {
        int j = i - 98304;
        float4 a = ((const float4*)g_pB[0])[j];
        float4 b = ((const float4*)g_pB[1])[j];
        ((float4*)g_base)[j] = make_float4(a.x + b.x, a.y + b.y, a.z + b.z, a.w + b.w);
    }
}

// ---------------- P0/P1/Q per (b,t), f32x2 ----------------
#define PG 4
__global__ void __launch_bounds__(256) k_P(const float* __restrict__ coords,
                                           const float* __restrict__ vis) {
    __shared__ float2 sv2[PG][256];   // (v, v)
    __shared__ float2 sxy[PG][256];   // (v*x, v*y)
    const int grp = blockIdx.x;   // 64 groups of PG bt
    const int ot  = blockIdx.y;   // 3 o-tiles of 256
    const int tid = threadIdx.x;
    const int o = ot * 256 + tid;

    for (int e = tid; e < PG * 256; e += 256) {
        int g = e >> 8, j = e & 255;
        int bt = grp * PG + g;
        int b = bt >> 6, t = bt & 63;
        int ci = ((b * 256 + j) * 64 + t) * 2;
        float x = coords[ci], y = coords[ci + 1];
        float v = vis[(b * 256 + j) * 64 + t];
        if (isnan(x)) { v = 0.f; x = 0.f; }
        if (isnan(y)) y = 0.f;
        sv2[g][j] = make_float2(v, v);
        sxy[g][j] = make_float2(v * x, v * y);
    }
    __syncthreads();

    u64 p01[PG], q2[PG];
#pragma unroll
    for (int g = 0; g < PG; ++g) { p01[g] = 0ull; q2[g] = 0ull; }

#pragma unroll 4
    for (int j = 0; j < 256; ++j) {
        u64 u = *(const u64*)(g_U2 + (j * DOUT + o) * 2);   // (u0, u1)
#pragma unroll
        for (int g = 0; g < PG; ++g) {
            u64 v2 = *(const u64*)(&sv2[g][j]);
            u64 xy = *(const u64*)(&sxy[g][j]);
            p01[g] = fma2(v2, u, p01[g]);   // (p0 += v*u0, p1 += v*u1)
            q2[g]  = fma2(xy, u, q2[g]);    // (qx += vx*u0, qy += vy*u1)
        }
    }
#pragma unroll
    for (int g = 0; g < PG; ++g) {
        int bt = grp * PG + g;
        float2 p = upk(p01[g]);
        float2 q = upk(q2[g]);
        g_P0[bt * DOUT + o] = p.x;
        g_P1[bt * DOUT + o] = p.y;
        g_Q [bt * DOUT + o] = q.x + q.y;
    }
}

// ---------------- out[bt,m,o] = vis_m*(cx_m*P0 + cy_m*P1 - Q) + base[m,o] + C[o] ----------------
// Software-pipelined: P loads for bt+1 issued before the compute/store block of bt.
__global__ void __launch_bounds__(256) k_out(const float* __restrict__ coords,
                                             const float* __restrict__ vis,
                                             float* __restrict__ out) {
    __shared__ float2 ss0[8][16];   // (v*x, v*x)
    __shared__ float2 ss1[8][16];   // (v*y, v*y)
    __shared__ float2 ss2[8][16];   // (-v, -v)
    const int mg0 = blockIdx.x * 16;  // 16 m-groups
    const int ot  = blockIdx.y;       // 3 o-tiles (256 each)
    const int btc = blockIdx.z * 8;   // 32 bt-chunks of 8
    const int tid = threadIdx.x;

    if (tid < 128) {
        int btl = tid >> 4, ml = tid & 15;
        int bt = btc + btl;
        int b = bt >> 6, t = bt & 63;
        int m = mg0 + ml;
        int ci = ((b * 256 + m) * 64 + t) * 2;
        float x = coords[ci], y = coords[ci + 1];
        float v = vis[(b * 256 + m) * 64 + t];
        if (isnan(x)) { v = 0.f; x = 0.f; }
        if (isnan(y)) y = 0.f;
        ss0[btl][ml] = make_float2(v * x, v * x);
        ss1[btl][ml] = make_float2(v * y, v * y);
        ss2[btl][ml] = make_float2(-v, -v);
    }
    __syncthreads();

    const int oq  = tid & 63;
    const int mg  = tid >> 6;        // 0..3
    const int o   = ot * 256 + oq * 4;
    const int ml0 = mg * 4;

    ulonglong2 cc = *(const ulonglong2*)(g_C + o);
    u64 baseC[4][2];
#pragma unroll
    for (int r = 0; r < 4; ++r) {
        ulonglong2 bv = *(const ulonglong2*)(g_base + (mg0 + ml0 + r) * DOUT + o);
        baseC[r][0] = add2(bv.x, cc.x);
        baseC[r][1] = add2(bv.y, cc.y);
    }

    // prologue: load P for first bt
    const int off0 = btc * DOUT + o;
    ulonglong2 p0 = *(const ulonglong2*)(g_P0 + off0);
    ulonglong2 p1 = *(const ulonglong2*)(g_P1 + off0);
    ulonglong2 qv = *(const ulonglong2*)(g_Q  + off0);

#pragma unroll
    for (int btl = 0; btl < 8; ++btl) {
        // prefetch next bt's P before consuming current
        ulonglong2 np0, np1, nqv;
        if (btl < 7) {
            const int offn = (btc + btl + 1) * DOUT + o;
            np0 = *(const ulonglong2*)(g_P0 + offn);
            np1 = *(const ulonglong2*)(g_P1 + offn);
            nqv = *(const ulonglong2*)(g_Q  + offn);
        }
        const int bt = btc + btl;
#pragma unroll
        for (int r = 0; r < 4; ++r) {
            u64 a2 = *(const u64*)(&ss0[btl][ml0 + r]);
            u64 b2 = *(const u64*)(&ss1[btl][ml0 + r]);
            u64 c2 = *(const u64*)(&ss2[btl][ml0 + r]);
            u64 o0 = fma2(a2, p0.x, fma2(b2, p1.x, fma2(c2, qv.x, baseC[r][0])));
            u64 o1 = fma2(a2, p0.y, fma2(b2, p1.y, fma2(c2, qv.y, baseC[r][1])));
            float* dst = out + ((bt * 256 + mg0 + ml0 + r) * DOUT) + o;
            asm volatile("st.global.cs.v2.u64 [%0], {%1, %2};"
                         :: "l"(dst), "l"(o0), "l"(o1) : "memory");
        }
        if (btl < 7) { p0 = np0; p1 = np1; qv = nqv; }
    }
}

extern "C" void kernel_launch(void* const* d_in, const int* in_sizes, int n_in,
                              void* d_out, int out_size) {
    const float* coords = (const float*)d_in[0];  // (4,256,64,2)
    const float* vis    = (const float*)d_in[1];  // (4,256,64)
    const float* pe     = (const float*)d_in[2];  // (256,512)
    const float* W1     = (const float*)d_in[3];  // (512,512)
    const float* b1     = (const float*)d_in[4];  // (512,)
    const float* W2     = (const float*)d_in[5];  // (1024,768)
    const float* b2     = (const float*)d_in[6];  // (768,)
    float* out = (float*)d_out;                   // (4,64,256,768)

    k_gemm<<<dim3(12, 13, 2), 256>>>(W1, pe, W2, b1, b2);
    k_red <<<576, 256>>>();
    k_P   <<<dim3(64, 3),  256>>>(coords, vis);
    k_out <<<dim3(16, 3, 32), 256>>>(coords, vis, out);
}

// round 15
// speedup vs baseline: 1.6413x; 1.0187x over previous
#include <cuda_runtime.h>
#include <math.h>

// B=4, M=256, T=64; fc1: 512->512, fc_out: 1024->768
#define DOUT 768
#define NBT  256   // B*T
#define KSPLIT 4

typedef unsigned long long u64;

__device__ __forceinline__ u64 fma2(u64 a, u64 b, u64 c) {
    u64 d; asm("fma.rn.f32x2 %0, %1, %2, %3;" : "=l"(d) : "l"(a), "l"(b), "l"(c)); return d;
}
__device__ __forceinline__ u64 add2(u64 a, u64 b) {
    u64 d; asm("add.rn.f32x2 %0, %1, %2;" : "=l"(d) : "l"(a), "l"(b)); return d;
}
__device__ __forceinline__ float2 upk(u64 a) {
    float2 f; asm("mov.b64 {%0, %1}, %2;" : "=f"(f.x), "=f"(f.y) : "l"(a)); return f;
}

__device__ float g_U2[512 * DOUT];    // interleaved: [(j*DOUT+o)*2+d] = U[2j+d, o]
__device__ float g_base[256 * DOUT];  // pos_embed @ W2[512:]
__device__ float g_C[DOUT];           // b1 @ W2[:512] + b2
__device__ float g_P0[NBT * DOUT];
__device__ float g_P1[NBT * DOUT];
__device__ float g_Q [NBT * DOUT];
// split-K partials
__device__ float g_pU[KSPLIT][512 * DOUT];
__device__ float g_pB[KSPLIT][256 * DOUT];

// ---------------- fused GEMM, scalar FFMA, split-K over blockIdx.z ----------------
// grid (12, 13, 4), block 256: each z covers K-chunk of 128.
__global__ void __launch_bounds__(256) k_gemm(
        const float* __restrict__ W1, const float* __restrict__ pe,
        const float* __restrict__ W2,
        const float* __restrict__ b1, const float* __restrict__ b2) {
    const int col0 = blockIdx.x * 64;
    const int kz   = blockIdx.z;           // K chunk: 0..3
    const int tid  = threadIdx.x;

    if (blockIdx.y == 12) {
        if (kz != 0) return;
        __shared__ float red[4][64];
        const int col = tid & 63;
        const int sub = tid >> 6;          // 0..3, 128 n each
        float acc = 0.f;
        const int n0 = sub * 128;
#pragma unroll 4
        for (int i = 0; i < 128; ++i)
            acc = fmaf(b1[n0 + i], W2[(n0 + i) * DOUT + col0 + col], acc);
        red[sub][col] = acc;
        __syncthreads();
        if (sub == 0)
            g_C[col0 + col] = red[0][col] + red[1][col] + red[2][col] + red[3][col] + b2[col0 + col];
        return;
    }

    __shared__ float As[16][68];   // transposed A tile: As[k][m], padded
    __shared__ float Bs[16][64];   // Bs[k][n]
    const int row0 = blockIdx.y * 64;
    const bool isU = (row0 < 512);
    const float* A = (isU ? (W1 + row0 * 512) : (pe + (row0 - 512) * 512)) + kz * 128;
    const int koff = (isU ? 0 : 512) + kz * 128;

    const int tm = (tid >> 4) * 4;     // 0..60 (m within tile)
    const int tn = (tid & 15) * 4;     // 0..60 (n within tile)

    const int ar = tid >> 2;           // 0..63 A row
    const int ac = (tid & 3) * 4;      // 0,4,8,12 A k-offset
    const int bk = tid >> 6;           // 0..3
    const int bj = tid & 63;           // 0..63

    float acc[4][4];
#pragma unroll
    for (int i = 0; i < 4; ++i)
#pragma unroll
        for (int j = 0; j < 4; ++j) acc[i][j] = 0.f;

    // prefetch first tiles into registers
    float4 a4 = *(const float4*)(A + ar * 512 + ac);
    float  b4[4];
#pragma unroll
    for (int r = 0; r < 4; ++r)
        b4[r] = W2[(koff + bk + r * 4) * DOUT + col0 + bj];

    for (int k0 = 0; k0 < 128; k0 += 16) {
        As[ac + 0][ar] = a4.x;
        As[ac + 1][ar] = a4.y;
        As[ac + 2][ar] = a4.z;
        As[ac + 3][ar] = a4.w;
#pragma unroll
        for (int r = 0; r < 4; ++r)
            Bs[bk + r * 4][bj] = b4[r];
        __syncthreads();

        if (k0 + 16 < 128) {
            a4 = *(const float4*)(A + ar * 512 + k0 + 16 + ac);
#pragma unroll
            for (int r = 0; r < 4; ++r)
                b4[r] = W2[(koff + k0 + 16 + bk + r * 4) * DOUT + col0 + bj];
        }

#pragma unroll
        for (int k = 0; k < 16; ++k) {
            float4 av = *(const float4*)(&As[k][tm]);
            float4 bv = *(const float4*)(&Bs[k][tn]);
            acc[0][0] = fmaf(av.x, bv.x, acc[0][0]); acc[0][1] = fmaf(av.x, bv.y, acc[0][1]);
            acc[0][2] = fmaf(av.x, bv.z, acc[0][2]); acc[0][3] = fmaf(av.x, bv.w, acc[0][3]);
            acc[1][0] = fmaf(av.y, bv.x, acc[1][0]); acc[1][1] = fmaf(av.y, bv.y, acc[1][1]);
            acc[1][2] = fmaf(av.y, bv.z, acc[1][2]); acc[1][3] = fmaf(av.y, bv.w, acc[1][3]);
            acc[2][0] = fmaf(av.z, bv.x, acc[2][0]); acc[2][1] = fmaf(av.z, bv.y, acc[2][1]);
            acc[2][2] = fmaf(av.z, bv.z, acc[2][2]); acc[2][3] = fmaf(av.z, bv.w, acc[2][3]);
            acc[3][0] = fmaf(av.w, bv.x, acc[3][0]); acc[3][1] = fmaf(av.w, bv.y, acc[3][1]);
            acc[3][2] = fmaf(av.w, bv.z, acc[3][2]); acc[3][3] = fmaf(av.w, bv.w, acc[3][3]);
        }
        __syncthreads();
    }

    if (isU) {
        float* dst = g_pU[kz];
#pragma unroll
        for (int i = 0; i < 4; ++i) {
            int gr = row0 + tm + i;
            int j = gr >> 1, d = gr & 1;
#pragma unroll
            for (int c = 0; c < 4; ++c)
                dst[(j * DOUT + col0 + tn + c) * 2 + d] = acc[i][c];
        }
    } else {
        float* dst = g_pB[kz];
#pragma unroll
        for (int i = 0; i < 4; ++i) {
            float4 v = make_float4(acc[i][0], acc[i][1], acc[i][2], acc[i][3]);
            *(float4*)(dst + (row0 - 512 + tm + i) * DOUT + col0 + tn) = v;
        }
    }
}

// ---------------- reduce split-K partials ----------------
// 98304 float4 for U2, 49152 float4 for base; grid 576 x 256
__global__ void __launch_bounds__(256) k_red() {
    const int i = blockIdx.x * 256 + threadIdx.x;   // float4 index
    if (i < 98304) {
        float4 s = ((const float4*)g_pU[0])[i];
#pragma unroll
        for (int z = 1; z < KSPLIT; ++z) {
            float4 a = ((const float4*)g_pU[z])[i];
            s.x += a.x; s.y += a.y; s.z += a.z; s.w += a.w;
        }
        ((float4*)g_U2)[i] = s;
    } else {
        int j = i - 98304;
        float4 s = ((const float4*)g_pB[0])[j];
#pragma unroll
        for (int z = 1; z < KSPLIT; ++z) {
            float4 a = ((const float4*)g_pB[z])[j];
            s.x += a.x; s.y += a.y; s.z += a.z; s.w += a.w;
        }
        ((float4*)g_base)[j] = s;
    }
}

// ---------------- P0/P1/Q per (b,t), f32x2, packed smem + U prefetch ----------------
#define PG 4
__global__ void __launch_bounds__(256) k_P(const float* __restrict__ coords,
                                           const float* __restrict__ vis) {
    __shared__ float4 sq[PG][256];   // (v, v, v*x, v*y)
    const int grp = blockIdx.x;   // 64 groups of PG bt
    const int ot  = blockIdx.y;   // 3 o-tiles of 256
    const int tid = threadIdx.x;
    const int o = ot * 256 + tid;

    for (int e = tid; e < PG * 256; e += 256) {
        int g = e >> 8, j = e & 255;
        int bt = grp * PG + g;
        int b = bt >> 6, t = bt & 63;
        int ci = ((b * 256 + j) * 64 + t) * 2;
        float x = coords[ci], y = coords[ci + 1];
        float v = vis[(b * 256 + j) * 64 + t];
        if (isnan(x)) { v = 0.f; x = 0.f; }
        if (isnan(y)) y = 0.f;
        sq[g][j] = make_float4(v, v, v * x, v * y);
    }
    __syncthreads();

    u64 p01[PG], q2[PG];
#pragma unroll
    for (int g = 0; g < PG; ++g) { p01[g] = 0ull; q2[g] = 0ull; }

    const float* Ubase = g_U2 + o * 2;
    u64 u = *(const u64*)(Ubase);                  // j = 0
#pragma unroll 4
    for (int j = 0; j < 256; ++j) {
        u64 un = 0ull;
        if (j < 255) un = *(const u64*)(Ubase + (j + 1) * DOUT * 2);
#pragma unroll
        for (int g = 0; g < PG; ++g) {
            ulonglong2 s = *(const ulonglong2*)(&sq[g][j]);  // s.x=(v,v), s.y=(vx,vy)
            p01[g] = fma2(s.x, u, p01[g]);
            q2[g]  = fma2(s.y, u, q2[g]);
        }
        u = un;
    }
#pragma unroll
    for (int g = 0; g < PG; ++g) {
        int bt = grp * PG + g;
        float2 p = upk(p01[g]);
        float2 q = upk(q2[g]);
        g_P0[bt * DOUT + o] = p.x;
        g_P1[bt * DOUT + o] = p.y;
        g_Q [bt * DOUT + o] = q.x + q.y;
    }
}

// ---------------- out[bt,m,o] = vis_m*(cx_m*P0 + cy_m*P1 - Q) + base[m,o] + C[o] ----------------
// Software-pipelined: P loads for bt+1 issued before the compute/store block of bt.
__global__ void __launch_bounds__(256) k_out(const float* __restrict__ coords,
                                             const float* __restrict__ vis,
                                             float* __restrict__ out) {
    __shared__ float2 ss0[8][16];   // (v*x, v*x)
    __shared__ float2 ss1[8][16];   // (v*y, v*y)
    __shared__ float2 ss2[8][16];   // (-v, -v)
    const int mg0 = blockIdx.x * 16;  // 16 m-groups
    const int ot  = blockIdx.y;       // 3 o-tiles (256 each)
    const int btc = blockIdx.z * 8;   // 32 bt-chunks of 8
    const int tid = threadIdx.x;

    if (tid < 128) {
        int btl = tid >> 4, ml = tid & 15;
        int bt = btc + btl;
        int b = bt >> 6, t = bt & 63;
        int m = mg0 + ml;
        int ci = ((b * 256 + m) * 64 + t) * 2;
        float x = coords[ci], y = coords[ci + 1];
        float v = vis[(b * 256 + m) * 64 + t];
        if (isnan(x)) { v = 0.f; x = 0.f; }
        if (isnan(y)) y = 0.f;
        ss0[btl][ml] = make_float2(v * x, v * x);
        ss1[btl][ml] = make_float2(v * y, v * y);
        ss2[btl][ml] = make_float2(-v, -v);
    }
    __syncthreads();

    const int oq  = tid & 63;
    const int mg  = tid >> 6;        // 0..3
    const int o   = ot * 256 + oq * 4;
    const int ml0 = mg * 4;

    ulonglong2 cc = *(const ulonglong2*)(g_C + o);
    u64 baseC[4][2];
#pragma unroll
    for (int r = 0; r < 4; ++r) {
        ulonglong2 bv = *(const ulonglong2*)(g_base + (mg0 + ml0 + r) * DOUT + o);
        baseC[r][0] = add2(bv.x, cc.x);
        baseC[r][1] = add2(bv.y, cc.y);
    }

    // prologue: load P for first bt
    const int off0 = btc * DOUT + o;
    ulonglong2 p0 = *(const ulonglong2*)(g_P0 + off0);
    ulonglong2 p1 = *(const ulonglong2*)(g_P1 + off0);
    ulonglong2 qv = *(const ulonglong2*)(g_Q  + off0);

#pragma unroll
    for (int btl = 0; btl < 8; ++btl) {
        // prefetch next bt's P before consuming current
        ulonglong2 np0, np1, nqv;
        if (btl < 7) {
            const int offn = (btc + btl + 1) * DOUT + o;
            np0 = *(const ulonglong2*)(g_P0 + offn);
            np1 = *(const ulonglong2*)(g_P1 + offn);
            nqv = *(const ulonglong2*)(g_Q  + offn);
        }
        const int bt = btc + btl;
#pragma unroll
        for (int r = 0; r < 4; ++r) {
            u64 a2 = *(const u64*)(&ss0[btl][ml0 + r]);
            u64 b2 = *(const u64*)(&ss1[btl][ml0 + r]);
            u64 c2 = *(const u64*)(&ss2[btl][ml0 + r]);
            u64 o0 = fma2(a2, p0.x, fma2(b2, p1.x, fma2(c2, qv.x, baseC[r][0])));
            u64 o1 = fma2(a2, p0.y, fma2(b2, p1.y, fma2(c2, qv.y, baseC[r][1])));
            float* dst = out + ((bt * 256 + mg0 + ml0 + r) * DOUT) + o;
            asm volatile("st.global.cs.v2.u64 [%0], {%1, %2};"
                         :: "l"(dst), "l"(o0), "l"(o1) : "memory");
        }
        if (btl < 7) { p0 = np0; p1 = np1; qv = nqv; }
    }
}

extern "C" void kernel_launch(void* const* d_in, const int* in_sizes, int n_in,
                              void* d_out, int out_size) {
    const float* coords = (const float*)d_in[0];  // (4,256,64,2)
    const float* vis    = (const float*)d_in[1];  // (4,256,64)
    const float* pe     = (const float*)d_in[2];  // (256,512)
    const float* W1     = (const float*)d_in[3];  // (512,512)
    const float* b1     = (const float*)d_in[4];  // (512,)
    const float* W2     = (const float*)d_in[5];  // (1024,768)
    const float* b2     = (const float*)d_in[6];  // (768,)
    float* out = (float*)d_out;                   // (4,64,256,768)

    k_gemm<<<dim3(12, 13, KSPLIT), 256>>>(W1, pe, W2, b1, b2);
    k_red <<<576, 256>>>();
    k_P   <<<dim3(64, 3),  256>>>(coords, vis);
    k_out <<<dim3(16, 3, 32), 256>>>(coords, vis, out);
}